// round 1
// baseline (speedup 1.0000x reference)
#include <cuda_runtime.h>

typedef unsigned long long ull;

// ---- packed f32x2 helpers (Blackwell FFMA2 path: only reachable via PTX) ----
__device__ __forceinline__ ull pk(float lo, float hi){
  ull r; asm("mov.b64 %0, {%1, %2};" : "=l"(r) : "f"(lo), "f"(hi)); return r;
}
__device__ __forceinline__ float2 upk(ull v){
  float2 r; asm("mov.b64 {%0, %1}, %2;" : "=f"(r.x), "=f"(r.y) : "l"(v)); return r;
}
__device__ __forceinline__ ull f2fma(ull a, ull b, ull c){
  ull d; asm("fma.rn.f32x2 %0, %1, %2, %3;" : "=l"(d) : "l"(a), "l"(b), "l"(c)); return d;
}

namespace cv {
constexpr int B = 4, C = 128, H = 128, W = 256, D = 81;
constexpr int HT = 4;     // output rows per block
constexpr int WT = 64;    // output cols per block
constexpr int XR = 12;    // x2 halo rows  (HT + 2*4)
constexpr int XC = 80;    // x2 halo cols, padded stride (72 used = WT + 2*4)
constexpr int NT = 192;   // 16 w-cols * 4 h * 3 i-groups
constexpr int PIPE = 3;
constexpr int HW = H * W;
}
using namespace cv;

__global__ __launch_bounds__(NT, 2)
void costvol_kernel(const float* __restrict__ x1g,
                    const float* __restrict__ x2g,
                    float* __restrict__ outg)
{
  __shared__ __align__(16) float x2s[PIPE][XR][XC];
  __shared__ __align__(16) float x1s[PIPE][HT][WT];

  const int tid = threadIdx.x;
  const int tc  = tid & 15;          // w-column group: owns w0+4*tc .. +3
  const int hl  = (tid >> 4) & 3;    // local h row
  const int ig  = tid >> 6;          // i-group 0..2 -> i in {3ig-4, 3ig-3, 3ig-2}

  const int w0 = blockIdx.x * WT;
  const int h0 = blockIdx.y * HT;
  const int b  = blockIdx.z;

  // ---------- staging descriptors (fixed per thread, no divisions) ----------
  // x2 halo: row = tid/16 (0..11), cols (tid&15) + 16u, u=0..4 (u=4: only tc<8)
  const int  srow  = tid >> 4;                    // 0..11
  const int  gh2   = h0 - 4 + srow;
  const bool rv    = (unsigned)gh2 < (unsigned)H;
  const int  x2row = (b * C * H + gh2) * W;
  const int  gc0   = w0 - 4 + tc;
  const bool u4ok  = tc < 8;

  // x1 tile: slot0 = element tid, slot1 = element tid+192 (only tid<64)
  const int  a0r = tid >> 6,          a0c = tid & 63;
  const int  a1r = (tid + NT) >> 6,   a1c = (tid + NT) & 63;
  const bool a1v = tid < (HT * WT - NT);
  const int  x1base = (b * C * H + h0) * W + w0;

  auto stage = [&](int c, int slot){
    const int cb2 = x2row + c * HW;
    #pragma unroll
    for (int u = 0; u < 4; u++){
      const int gc = gc0 + 16 * u;
      float v = (rv && (unsigned)gc < (unsigned)W) ? __ldg(x2g + cb2 + gc) : 0.f;
      x2s[slot][srow][tc + 16 * u] = v;
    }
    if (u4ok){
      const int gc = gc0 + 64;
      float v = (rv && (unsigned)gc < (unsigned)W) ? __ldg(x2g + cb2 + gc) : 0.f;
      x2s[slot][srow][tc + 64] = v;
    }
    const int cb1 = x1base + c * HW;
    x1s[slot][a0r][a0c] = __ldg(x1g + cb1 + a0r * W + a0c);
    if (a1v) x1s[slot][a1r][a1c] = __ldg(x1g + cb1 + a1r * W + a1c);
  };

  // 3 i * 9 j * 2 w-pairs packed accumulators (108 regs)
  ull acc[3][9][2];
  #pragma unroll
  for (int s = 0; s < 3; s++)
    #pragma unroll
    for (int jj = 0; jj < 9; jj++){ acc[s][jj][0] = 0ull; acc[s][jj][1] = 0ull; }

  stage(0, 0);
  stage(1, 1);
  __syncthreads();

  int slot_c = 0, slot_s = 2;
  for (int c = 0; c < C; c++){
    if (c + 2 < C) stage(c + 2, slot_s);

    // x1 pair constants for this channel: (w,w+1) and (w+2,w+3)
    const float4 a4 = *(const float4*)&x1s[slot_c][hl][tc * 4];
    const ull ap0 = pk(a4.x, a4.y);
    const ull ap1 = pk(a4.z, a4.w);

    #pragma unroll
    for (int s = 0; s < 3; s++){
      // i = 3*ig + s - 4 ; smem row of x2[h - i]
      const int rr = hl + 8 - 3 * ig - s;
      const float* rp = &x2s[slot_c][rr][tc * 4];
      const float4 b0 = *(const float4*)(rp);
      const float4 b1 = *(const float4*)(rp + 4);
      const float4 b2 = *(const float4*)(rp + 8);
      const float f[12] = {b0.x, b0.y, b0.z, b0.w,
                           b1.x, b1.y, b1.z, b1.w,
                           b2.x, b2.y, b2.z, b2.w};
      // overlapping pairs pr[t] = (f[t], f[t+1]); even t elide to reg pairs
      ull pr[11];
      #pragma unroll
      for (int t = 0; t < 11; t++) pr[t] = pk(f[t], f[t + 1]);

      #pragma unroll
      for (int jj = 0; jj < 9; jj++){
        // j = jj-4 ; lane cc = w' - j -> pair index t = 4 - j (+2 for 2nd pair)
        acc[s][jj][0] = f2fma(ap0, pr[8  - jj], acc[s][jj][0]);
        acc[s][jj][1] = f2fma(ap1, pr[10 - jj], acc[s][jj][1]);
      }
    }
    __syncthreads();
    slot_c = (slot_c == PIPE - 1) ? 0 : slot_c + 1;
    slot_s = (slot_s == PIPE - 1) ? 0 : slot_s + 1;
  }

  // ---------------- epilogue: scale by 1/81 and store ----------------
  const float invD = 1.0f / 81.0f;
  const int h = h0 + hl;
  const int w = w0 + tc * 4;
  #pragma unroll
  for (int s = 0; s < 3; s++){
    const int i = 3 * ig + s - 4;
    #pragma unroll
    for (int jj = 0; jj < 9; jj++){
      const int j = jj - 4;
      const int k = (9 * i + j + 81) % 81;   // python-mod wraparound
      const float2 p0 = upk(acc[s][jj][0]);
      const float2 p1 = upk(acc[s][jj][1]);
      const float4 o = make_float4(p0.x * invD, p0.y * invD,
                                   p1.x * invD, p1.y * invD);
      *(float4*)&outg[((size_t)(b * D + k) * H + h) * W + w] = o;
    }
  }
}

extern "C" void kernel_launch(void* const* d_in, const int* in_sizes, int n_in,
                              void* d_out, int out_size)
{
  const float* x1 = (const float*)d_in[0];
  const float* x2 = (const float*)d_in[1];
  float* out = (float*)d_out;
  dim3 grid(W / WT, H / HT, B);   // (4, 32, 4) = 512 blocks
  costvol_kernel<<<grid, NT>>>(x1, x2, out);
}